// round 14
// baseline (speedup 1.0000x reference)
#include <cuda_runtime.h>
#include <cuda_fp16.h>
#include <cuda.h>
#include <cstdint>
#include <cstddef>

#define IN_F   4096
#define OUT_F  4096
#define MROWS  4096
#define RANK   32
#define KDIM   4096
#define TK     64
#define NKT    64
#define MO     128         // out-features per CTA (sparse A rows)
#define NM     128         // x-rows per CTA (B cols)
#define PSTG   3
#define KSPLIT 8
#define NTHR   288         // 8 consumer warps + 1 producer

#define A_STAGE_BYTES (MO*(TK/2)*2)     // 8192 (compressed, 64B rows)
#define B_STAGE_BYTES (NM*TK*2)         // 16384 (128B rows)
#define M_STAGE_BYTES 1024              // meta: 4 c-cols x 64 p x 4B
#define STAGE_BYTES   (A_STAGE_BYTES + B_STAGE_BYTES + M_STAGE_BYTES)  // 25600
#define SMEM_HDR      1024
#define OFF_LB        1024                          // 128*32*2 = 8192
#define OFF_T         (OFF_LB + MO*RANK*2)          // 9216; 128*32*2 = 8192
#define OFF_STAGE0    (OFF_T + NM*RANK*2)           // 17408
#define SMEM_TOTAL    (OFF_STAGE0 + PSTG*STAGE_BYTES)  // 94208 -> 2 CTAs/SM

__device__ __half   g_xq  [(size_t)MROWS * KDIM];
__device__ __half   g_xs  [(size_t)MROWS * IN_F];
__device__ __half   g_wc  [(size_t)OUT_F * (KDIM/2)];      // compressed 2:4 values
__device__ uint32_t g_meta[(size_t)(KDIM/16) * (OUT_F/2)]; // [256 c][2048 p, 64-perm]
__device__ __half   g_lah [(size_t)RANK * IN_F];
__device__ __half   g_lbh [(size_t)OUT_F * RANK];
__device__ float    g_tp  [(size_t)KSPLIT * MROWS * RANK];

__device__ __forceinline__ uint32_t smem_u32(const void* p) {
    uint32_t a;
    asm("{ .reg .u64 t; cvta.to.shared.u64 t, %1; cvt.u32.u64 %0, t; }" : "=r"(a) : "l"(p));
    return a;
}

#define MBAR_INIT(addr, cnt) \
    asm volatile("mbarrier.init.shared.b64 [%0], %1;" :: "r"(addr), "r"((uint32_t)(cnt)) : "memory")
#define MBAR_EXPECT_TX(addr, b) \
    asm volatile("mbarrier.arrive.expect_tx.shared.b64 _, [%0], %1;" :: "r"(addr), "r"((uint32_t)(b)) : "memory")
#define MBAR_ARRIVE(addr) \
    asm volatile("mbarrier.arrive.shared.b64 _, [%0];" :: "r"(addr) : "memory")
#define MBAR_WAIT(addr, ph) do {                                              \
    uint32_t _m = (addr), _p = (uint32_t)(ph), _d;                            \
    asm volatile("{\n\t.reg .pred p;\n\t"                                     \
        "mbarrier.try_wait.parity.acquire.cta.shared::cta.b64 p, [%1], %2;\n\t" \
        "selp.b32 %0, 1, 0, p;\n\t}"                                          \
        : "=r"(_d) : "r"(_m), "r"(_p) : "memory");                            \
    if (!_d) {                                                                \
        asm volatile("{\n\t.reg .pred P1;\n\t"                                \
            "WL%=:\n\t"                                                       \
            "mbarrier.try_wait.parity.acquire.cta.shared::cta.b64 P1, [%0], %1, 0x989680;\n\t" \
            "@P1 bra.uni WD%=;\n\t"                                           \
            "bra.uni WL%=;\n\t"                                               \
            "WD%=:\n\t}" :: "r"(_m), "r"(_p) : "memory");                     \
    }                                                                         \
} while (0)

__device__ __forceinline__ void tma_load_2d(uint32_t smem_addr, const CUtensorMap* map,
                                            int cx, int cy, uint32_t mbar) {
    asm volatile(
        "cp.async.bulk.tensor.2d.shared::cta.global.tile.mbarrier::complete_tx::bytes "
        "[%0], [%1, {%2, %3}], [%4];"
        :: "r"(smem_addr), "l"((unsigned long long)(uintptr_t)map),
           "r"(cx), "r"(cy), "r"(mbar) : "memory");
}

__device__ __forceinline__ void ldsm_x4(uint32_t& r0, uint32_t& r1, uint32_t& r2, uint32_t& r3,
                                        uint32_t addr) {
    asm volatile("ldmatrix.sync.aligned.m8n8.x4.shared.b16 {%0,%1,%2,%3}, [%4];"
                 : "=r"(r0), "=r"(r1), "=r"(r2), "=r"(r3) : "r"(addr));
}

__device__ __forceinline__ void mma16816(float* c, const uint32_t* a, uint32_t b0, uint32_t b1) {
    asm volatile(
        "mma.sync.aligned.m16n8k16.row.col.f32.f16.f16.f32 "
        "{%0,%1,%2,%3}, {%4,%5,%6,%7}, {%8,%9}, {%0,%1,%2,%3};"
        : "+f"(c[0]), "+f"(c[1]), "+f"(c[2]), "+f"(c[3])
        : "r"(a[0]), "r"(a[1]), "r"(a[2]), "r"(a[3]), "r"(b0), "r"(b1));
}

__device__ __forceinline__ void mma_sp16832(float* c, const uint32_t* a, const uint32_t* b,
                                            uint32_t e) {
    asm volatile(
        "mma.sp::ordered_metadata.sync.aligned.m16n8k32.row.col.f32.f16.f16.f32 "
        "{%0,%1,%2,%3}, {%4,%5,%6,%7}, {%8,%9,%10,%11}, {%0,%1,%2,%3}, %12, 0x0;"
        : "+f"(c[0]), "+f"(c[1]), "+f"(c[2]), "+f"(c[3])
        : "r"(a[0]), "r"(a[1]), "r"(a[2]), "r"(a[3]),
          "r"(b[0]), "r"(b[1]), "r"(b[2]), "r"(b[3]), "r"(e));
}

// ---- prologue: compress W into 2:4 values + ordered metadata (permuted layout) ----
__device__ __forceinline__ float sel4(float v0, float v1, float v2, float v3, int i) {
    return (i == 0) ? v0 : (i == 1) ? v1 : (i == 2) ? v2 : v3;
}
__global__ void compress_w_kernel(const float* __restrict__ w,
                                  __half* __restrict__ wc,
                                  uint32_t* __restrict__ metap) {
    int idx = blockIdx.x * 256 + threadIdx.x;     // 2048 p * 256 c
    int p = idx >> 8;
    int c = idx & 255;
    int o0 = (p >> 3) * 16 + (p & 7);             // row pair (o0, o0+8)
    uint32_t meta32 = 0;
#pragma unroll
    for (int half_i = 0; half_i < 2; half_i++) {
        int o = o0 + half_i * 8;
        const float4* wr = reinterpret_cast<const float4*>(w + (size_t)o * KDIM + c * 16);
        __align__(16) __half st[8];
        uint32_t m16 = 0;
#pragma unroll
        for (int g = 0; g < 4; g++) {
            float4 v = wr[g];
            unsigned nz = (v.x != 0.0f ? 1u : 0u) | (v.y != 0.0f ? 2u : 0u)
                        | (v.z != 0.0f ? 4u : 0u) | (v.w != 0.0f ? 8u : 0u);
            int i0, i1;
            int n = __popc(nz);
            if (n >= 2) {
                i0 = __ffs(nz) - 1;
                unsigned rest = nz & ~(1u << i0);
                i1 = __ffs(rest) - 1;
            } else if (n == 1) {
                int ii = __ffs(nz) - 1;
                if (ii == 3) { i0 = 2; i1 = 3; }
                else         { i0 = ii; i1 = 3; }
            } else { i0 = 0; i1 = 1; }
            st[2*g]   = __float2half(sel4(v.x, v.y, v.z, v.w, i0));
            st[2*g+1] = __float2half(sel4(v.x, v.y, v.z, v.w, i1));
            m16 |= (uint32_t)(i0 | (i1 << 2)) << (4 * g);
        }
        reinterpret_cast<uint4*>(wc + (size_t)o * (KDIM/2) + c * 8)[0] =
            reinterpret_cast<uint4*>(st)[0];
        meta32 |= m16 << (16 * half_i);
    }
    // permute within 64-word group so GEMM can ld.shared.v4 its 4 mi-words
    int pl = p & 63;
    int blk = pl >> 5, q = pl & 7, mi = (pl >> 3) & 3;
    int pperm = (p & ~63) | (blk * 32 + q * 4 + mi);
    metap[(size_t)c * (OUT_F/2) + pperm] = meta32;
}

// ---- prologue: lora_a, lora_b -> fp16 ----
#define NL4 ((RANK * IN_F) / 4)
__global__ void prep_lora_kernel(const float4* __restrict__ la4,
                                 const float4* __restrict__ lb4,
                                 uint2* __restrict__ lah4,
                                 uint2* __restrict__ lbh4) {
    int idx = blockIdx.x * 256 + threadIdx.x;
    float4 v; uint2* dst;
    if (idx < NL4) { v = la4[idx];       dst = lah4 + idx; }
    else           { v = lb4[idx - NL4]; dst = lbh4 + (idx - NL4); }
    __half2 lo = __floats2half2_rn(v.x, v.y);
    __half2 hi = __floats2half2_rn(v.z, v.w);
    uint2 o;
    o.x = *reinterpret_cast<uint32_t*>(&lo);
    o.y = *reinterpret_cast<uint32_t*>(&hi);
    *dst = o;
}

// ---- prologue: smooth + exact NVFP4 fake-quant, 8 elems/thread ----
__global__ void quant_x_kernel(const float* __restrict__ x,
                               const float* __restrict__ ss,
                               __half* __restrict__ xs,
                               __half* __restrict__ xq) {
    int t = blockIdx.x * 256 + threadIdx.x;          // half-block index
    int row = t >> 9;                                // 512 half-blocks per row
    int kb  = (t & 511) << 3;                        // 8-elem offset
    const float4* xp = reinterpret_cast<const float4*>(x + (size_t)row * IN_F + kb);
    const float4* sp = reinterpret_cast<const float4*>(ss + kb);
    float v[8];
#pragma unroll
    for (int i = 0; i < 2; i++) {
        float4 a = xp[i]; float4 s = sp[i];
        v[4*i+0] = a.x * s.x; v[4*i+1] = a.y * s.y;
        v[4*i+2] = a.z * s.z; v[4*i+3] = a.w * s.w;
    }
    float amax = 0.0f;
#pragma unroll
    for (int i = 0; i < 8; i++) amax = fmaxf(amax, fabsf(v[i]));
    amax = fmaxf(amax, __shfl_xor_sync(0xffffffffu, amax, 1));   // pair = 16-elem block
    amax = fmaxf(amax, 1e-12f);
    float scale = amax / 6.0f;
    __align__(16) __half h_s[8];
    __align__(16) __half h_q[8];
#pragma unroll
    for (int i = 0; i < 8; i++) {
        h_s[i] = __float2half(v[i]);
        float an = fabsf(v[i]) / scale;
        float lvl;
        if      (an <= 0.25f) lvl = 0.0f;   // <= : tie -> lower level (argmin-first)
        else if (an <= 0.75f) lvl = 0.5f;
        else if (an <= 1.25f) lvl = 1.0f;
        else if (an <= 1.75f) lvl = 1.5f;
        else if (an <= 2.5f)  lvl = 2.0f;
        else if (an <= 3.5f)  lvl = 3.0f;
        else if (an <= 5.0f)  lvl = 4.0f;
        else                  lvl = 6.0f;
        h_q[i] = __float2half(copysignf(lvl * scale, v[i]));
    }
    reinterpret_cast<uint4*>(xs + (size_t)row * IN_F + kb)[0] =
        reinterpret_cast<uint4*>(h_s)[0];
    reinterpret_cast<uint4*>(xq + (size_t)row * KDIM + kb)[0] =
        reinterpret_cast<uint4*>(h_q)[0];
}

// ---- prologue: t partials via mma (split-K; reduce folded into GEMM) ----
#define LPSTG 2
#define L_A_BYTES (128*64*2)
#define L_B_BYTES (32*64*2)
#define L_STAGE   (L_A_BYTES + L_B_BYTES)
#define L_SMEM    (1024 + LPSTG*L_STAGE)
#define LOFF_FULL(s)  (16u + 8u * (s))
#define LOFF_EMPTY(s) (48u + 8u * (s))
#define LOFF_A(s)     (1024u + (s) * L_STAGE)
#define LOFF_B(s)     (LOFF_A(s) + L_A_BYTES)

__global__ void __launch_bounds__(160, 1)
lora_mma_kernel(const __grid_constant__ CUtensorMap tma_xs,
                const __grid_constant__ CUtensorMap tma_la,
                float* __restrict__ tp) {
    extern __shared__ __align__(1024) char smem_buf[];
    uint32_t sbase = smem_u32(smem_buf);
    int tid  = threadIdx.x;
    int warp = tid >> 5;
    int lane = tid & 31;
    int m0 = blockIdx.x * 128;
    int kz = blockIdx.y;
    int kt0 = kz * 8;

    if (tid == 0) {
        for (int s = 0; s < LPSTG; s++) {
            MBAR_INIT(sbase + LOFF_FULL(s), 1);
            MBAR_INIT(sbase + LOFF_EMPTY(s), 4);
        }
    }
    __syncthreads();

    if (warp == 4) {
        if (lane == 0) {
            int s = 0;
            for (int kt = 0; kt < 8; kt++) {
                if (kt >= LPSTG) MBAR_WAIT(sbase + LOFF_EMPTY(s), ((kt - LPSTG) / LPSTG) & 1);
                MBAR_EXPECT_TX(sbase + LOFF_FULL(s), L_STAGE);
                tma_load_2d(sbase + LOFF_A(s), &tma_xs, (kt0 + kt) * 64, m0, sbase + LOFF_FULL(s));
                tma_load_2d(sbase + LOFF_B(s), &tma_la, (kt0 + kt) * 64, 0,  sbase + LOFF_FULL(s));
                if (++s == LPSTG) s = 0;
            }
        }
        return;
    }

    int wm = warp * 32;
    int lrow = (lane & 7) + ((lane >> 3) & 1) * 8;
    int lhi  = (lane >> 4) & 1;
    uint32_t arow[2], asw[2], brow[2], bsw[2];
#pragma unroll
    for (int i = 0; i < 2; i++) {
        int ra = wm + i * 16 + lrow;
        arow[i] = (uint32_t)ra * 128u; asw[i] = (uint32_t)(ra & 7);
        int rb = i * 16 + lrow;
        brow[i] = (uint32_t)rb * 128u; bsw[i] = (uint32_t)(rb & 7);
    }
    float acc[2][4][4];
#pragma unroll
    for (int i = 0; i < 2; i++)
#pragma unroll
        for (int j = 0; j < 4; j++)
#pragma unroll
            for (int q = 0; q < 4; q++) acc[i][j][q] = 0.0f;

    int s = 0;
    for (int kt = 0; kt < 8; kt++) {
        MBAR_WAIT(sbase + LOFF_FULL(s), (kt / LPSTG) & 1);
        uint32_t aS = sbase + LOFF_A(s);
        uint32_t bS = sbase + LOFF_B(s);
#pragma unroll
        for (int ks = 0; ks < 4; ks++) {
            uint32_t chunk = (uint32_t)(ks * 2 + lhi);
            uint32_t a[2][4];
            uint32_t bf[4][2];
#pragma unroll
            for (int mi = 0; mi < 2; mi++)
                ldsm_x4(a[mi][0], a[mi][1], a[mi][2], a[mi][3],
                        aS + arow[mi] + (((chunk ^ asw[mi]) & 7u) << 4));
#pragma unroll
            for (int nj = 0; nj < 2; nj++) {
                uint32_t r0, r1, r2, r3;
                ldsm_x4(r0, r1, r2, r3,
                        bS + brow[nj] + (((chunk ^ bsw[nj]) & 7u) << 4));
                bf[2*nj][0] = r0; bf[2*nj][1] = r2;
                bf[2*nj+1][0] = r1; bf[2*nj+1][1] = r3;
            }
#pragma unroll
            for (int mi = 0; mi < 2; mi++)
#pragma unroll
                for (int ni = 0; ni < 4; ni++)
                    mma16816(acc[mi][ni], a[mi], bf[ni][0], bf[ni][1]);
        }
        if (lane == 0) MBAR_ARRIVE(sbase + LOFF_EMPTY(s));
        if (++s == LPSTG) s = 0;
    }

    float* tpb = tp + (size_t)kz * MROWS * RANK;
    int crow = lane >> 2;
    int ccol = (lane & 3) * 2;
#pragma unroll
    for (int mi = 0; mi < 2; mi++) {
        int m = m0 + wm + mi * 16 + crow;
#pragma unroll
        for (int ni = 0; ni < 4; ni++) {
            int c = ni * 8 + ccol;
            *reinterpret_cast<float2*>(tpb + (size_t)m * RANK + c) =
                make_float2(acc[mi][ni][0], acc[mi][ni][1]);
            *reinterpret_cast<float2*>(tpb + (size_t)(m + 8) * RANK + c) =
                make_float2(acc[mi][ni][2], acc[mi][ni][3]);
        }
    }
}

// ---- main sparse GEMM: MO=128 out x NM=128 m, 8 consumer warps (64x32), 2 CTA/SM ----
#define OFF_FULL(s)  (16u + 8u * (s))
#define OFF_EMPTY(s) (64u + 8u * (s))
#define OFF_A(s)     (OFF_STAGE0 + (s) * STAGE_BYTES)
#define OFF_B(s)     (OFF_A(s) + A_STAGE_BYTES)
#define OFF_M(s)     (OFF_B(s) + B_STAGE_BYTES)

__global__ void __launch_bounds__(NTHR, 2)
gemm_kernel(const __grid_constant__ CUtensorMap tma_a,
            const __grid_constant__ CUtensorMap tma_b,
            const __grid_constant__ CUtensorMap tma_m,
            const float* __restrict__ tp,
            const __half* __restrict__ lbh,
            const float* __restrict__ bias,
            float* __restrict__ out) {
    extern __shared__ __align__(1024) char smem_buf[];
    uint32_t sbase = smem_u32(smem_buf);
    int tid  = threadIdx.x;
    int warp = tid >> 5;
    int lane = tid & 31;
    int m0g = blockIdx.x * NM;     // x-rows base
    int mo0 = blockIdx.y * MO;     // out-features base

    // lb tile [MO x 32] fp16 (coop), t tile [NM x 32] fp16 built from partials
    {
        const uint4* lbg = reinterpret_cast<const uint4*>(lbh + (size_t)mo0 * RANK);
        uint4* lbs = reinterpret_cast<uint4*>(smem_buf + OFF_LB);
        for (int i = tid; i < MO * 4; i += NTHR) lbs[i] = lbg[i];
        for (int i = tid; i < NM * RANK; i += NTHR) {
            int r = i >> 5, c = i & 31;
            float s = 0.0f;
#pragma unroll
            for (int z = 0; z < KSPLIT; z++)
                s += tp[(size_t)z * MROWS * RANK + (size_t)(m0g + r) * RANK + c];
            *reinterpret_cast<__half*>(smem_buf + OFF_T + r * 64 + c * 2) = __float2half(s);
        }
    }
    if (tid == 0) {
        for (int s = 0; s < PSTG; s++) {
            MBAR_INIT(sbase + OFF_FULL(s), 1);
            MBAR_INIT(sbase + OFF_EMPTY(s), 8);
        }
    }
    __syncthreads();

    int wo = (warp & 1) * 64;       // out offset (A rows), 2 groups
    int wm = (warp >> 1) * 32;      // m offset (B cols), 4 groups  [warp 8 = producer]
    float acc[4][4][4];

    if (warp == 8) {
        if (lane == 0) {
            int s = 0;
            for (int kt = 0; kt < NKT; kt++) {
                if (kt >= PSTG) MBAR_WAIT(sbase + OFF_EMPTY(s), ((kt - PSTG) / PSTG) & 1);
                MBAR_EXPECT_TX(sbase + OFF_FULL(s), STAGE_BYTES);
                tma_load_2d(sbase + OFF_A(s), &tma_a, kt * (TK/2), mo0, sbase + OFF_FULL(s));
                tma_load_2d(sbase + OFF_B(s), &tma_b, kt * TK, m0g, sbase + OFF_FULL(s));
                tma_load_2d(sbase + OFF_M(s), &tma_m, mo0 >> 1, kt * 4, sbase + OFF_FULL(s));
                if (++s == PSTG) s = 0;
            }
        }
    } else {
#pragma unroll
        for (int i = 0; i < 4; i++)
#pragma unroll
            for (int j = 0; j < 4; j++)
#pragma unroll
                for (int q = 0; q < 4; q++) acc[i][j][q] = 0.0f;

        // A (compressed) lane addressing: 64B rows, SW64
        int Lm = lane >> 3;
        int amrow = (Lm & 1) * 8 + (lane & 7);
        int achunk_add = Lm >> 1;
        uint32_t arowb[4], akey[4];
#pragma unroll
        for (int mi = 0; mi < 4; mi++) {
            int r = wo + mi * 16 + amrow;
            arowb[mi] = (uint32_t)r * 64u;
            akey[mi]  = (uint32_t)((r >> 1) & 3);
        }
        // B lane addressing: 128B rows, SW128
        int lrow = (lane & 7) + ((lane >> 3) & 1) * 8;
        int lhi  = (lane >> 4) & 1;
        uint32_t browb[2], bkey[2];
#pragma unroll
        for (int g = 0; g < 2; g++) {
            int r = wm + g * 16 + lrow;
            browb[g] = (uint32_t)r * 128u;
            bkey[g]  = (uint32_t)(r & 7);
        }
        // metadata (smem, permuted): one v4 load per k32 step
        uint32_t mploc = (uint32_t)wo * 2u + ((uint32_t)(lane >> 2)) * 16u;
        uint32_t cpar  = (uint32_t)(lane & 1);

        int s = 0;
        for (int kt = 0; kt < NKT; kt++) {
            MBAR_WAIT(sbase + OFF_FULL(s), (kt / PSTG) & 1);
            uint32_t aS = sbase + OFF_A(s);
            uint32_t bS = sbase + OFF_B(s);
            uint32_t mS = sbase + OFF_M(s);
#pragma unroll
            for (int kk = 0; kk < 2; kk++) {
                uint32_t mreg[4];
                {
                    uint32_t maddr = mS + ((uint32_t)(kk * 2) + cpar) * 256u + mploc;
                    asm volatile("ld.shared.v4.b32 {%0,%1,%2,%3}, [%4];"
                                 : "=r"(mreg[0]), "=r"(mreg[1]), "=r"(mreg[2]), "=r"(mreg[3])
                                 : "r"(maddr));
                }
                uint32_t a[4][4];
#pragma unroll
                for (int mi = 0; mi < 4; mi++) {
                    uint32_t c = (uint32_t)(kk * 2 + achunk_add);
                    ldsm_x4(a[mi][0], a[mi][1], a[mi][2], a[mi][3],
                            aS + arowb[mi] + (((c ^ akey[mi]) & 3u) << 4));
                }
                uint32_t bf[4][4];
#pragma unroll
                for (int g = 0; g < 2; g++) {
#pragma unroll
                    for (int sub = 0; sub < 2; sub++) {
                        uint32_t chunk = (uint32_t)(kk * 4 + sub * 2 + lhi);
                        uint32_t r0, r1, r2, r3;
                        ldsm_x4(r0, r1, r2, r3,
                                bS + browb[g] + (((chunk ^ bkey[g]) & 7u) << 4));
                        bf[2*g][2*sub]     = r0; bf[2*g][2*sub+1]   = r2;
                        bf[2*g+1][2*sub]   = r1; bf[2*g+1][2*sub+1] = r3;
                    }
                }
#pragma unroll
                for (int mi = 0; mi < 4; mi++)
#pragma unroll
                    for (int ni = 0; ni < 4; ni++)
                        mma_sp16832(acc[mi][ni], a[mi], bf[ni], mreg[mi]);
            }
            if (lane == 0) MBAR_ARRIVE(sbase + OFF_EMPTY(s));
            if (++s == PSTG) s = 0;
        }

        // ---- LoRA correction: acc += lb_tile @ t_tile^T (dense, K=32) ----
        {
            uint32_t lbS = sbase + OFF_LB;
            uint32_t tS  = sbase + OFF_T;
#pragma unroll
            for (int kk = 0; kk < 2; kk++) {
                uint32_t a[4][4];
#pragma unroll
                for (int mi = 0; mi < 4; mi++) {
                    int r = wo + mi * 16 + amrow;
                    uint32_t c = (uint32_t)(kk * 2 + achunk_add);
                    ldsm_x4(a[mi][0], a[mi][1], a[mi][2], a[mi][3],
                            lbS + (uint32_t)r * 64u + (c << 4));
                }
                uint32_t bf[4][2];
#pragma unroll
                for (int g = 0; g < 2; g++) {
                    int r = wm + g * 16 + lrow;
                    uint32_t chunk = (uint32_t)(kk * 2 + lhi);
                    uint32_t r0, r1, r2, r3;
                    ldsm_x4(r0, r1, r2, r3, tS + (uint32_t)r * 64u + (chunk << 4));
                    bf[2*g][0] = r0; bf[2*g][1] = r2;
                    bf[2*g+1][0] = r1; bf[2*g+1][1] = r3;
                }
#pragma unroll
                for (int mi = 0; mi < 4; mi++)
#pragma unroll
                    for (int ni = 0; ni < 4; ni++)
                        mma16816(acc[mi][ni], a[mi], bf[ni][0], bf[ni][1]);
            }
        }
    }

    __syncthreads();   // all stages consumed; reuse smem for transpose

    if (warp < 8) {
        float* tw = reinterpret_cast<float*>(smem_buf + SMEM_HDR) + warp * (32 * 68);
        int crow = lane >> 2;
        int ccol = (lane & 3) * 2;
#pragma unroll
        for (int mi = 0; mi < 4; mi++) {
            int o0 = mi * 16 + crow;
#pragma unroll
            for (int ni = 0; ni < 4; ni++) {
                int ml = ni * 8 + ccol;
                tw[ml * 68 + o0]           = acc[mi][ni][0];
                tw[(ml + 1) * 68 + o0]     = acc[mi][ni][1];
                tw[ml * 68 + o0 + 8]       = acc[mi][ni][2];
                tw[(ml + 1) * 68 + o0 + 8] = acc[mi][ni][3];
            }
        }
        __syncwarp();
        int oc = (lane & 15) * 4;
        float4 bv = __ldg(reinterpret_cast<const float4*>(bias + mo0 + wo + oc));
#pragma unroll 4
        for (int it = 0; it < 16; it++) {
            int ml = it * 2 + (lane >> 4);
            float4 v = *reinterpret_cast<float4*>(tw + ml * 68 + oc);
            v.x += bv.x; v.y += bv.y; v.z += bv.z; v.w += bv.w;
            *reinterpret_cast<float4*>(out + (size_t)(m0g + wm + ml) * OUT_F + mo0 + wo + oc) = v;
        }
    }
}

typedef CUresult (*tmap_fn_t)(CUtensorMap*, CUtensorMapDataType, cuuint32_t, void*,
                              const cuuint64_t*, const cuuint64_t*, const cuuint32_t*,
                              const cuuint32_t*, CUtensorMapInterleave, CUtensorMapSwizzle,
                              CUtensorMapL2promotion, CUtensorMapFloatOOBfill);

static void make_map_f16(tmap_fn_t enc, CUtensorMap* m, void* ptr,
                         uint64_t d0, uint64_t d1, uint32_t b0, uint32_t b1,
                         CUtensorMapSwizzle sw) {
    cuuint64_t dims[2]    = {(cuuint64_t)d0, (cuuint64_t)d1};
    cuuint64_t strides[1] = {(cuuint64_t)d0 * 2};
    cuuint32_t es[2]      = {1, 1};
    cuuint32_t box[2]     = {b0, b1};
    enc(m, CU_TENSOR_MAP_DATA_TYPE_FLOAT16, 2, ptr, dims, strides, box, es,
        CU_TENSOR_MAP_INTERLEAVE_NONE, sw,
        CU_TENSOR_MAP_L2_PROMOTION_L2_128B, CU_TENSOR_MAP_FLOAT_OOB_FILL_NONE);
}

extern "C" void kernel_launch(void* const* d_in, const int* in_sizes, int n_in,
                              void* d_out, int out_size) {
    (void)in_sizes; (void)n_in; (void)out_size;
    const float* x      = (const float*)d_in[0];
    const float* smooth = (const float*)d_in[1];
    const float* w      = (const float*)d_in[2];
    const float* la     = (const float*)d_in[3];
    const float* lb     = (const float*)d_in[4];
    const float* bias   = (const float*)d_in[5];
    float* out = (float*)d_out;

    void *p_xq, *p_xs, *p_wc, *p_meta, *p_lah, *p_lbh, *p_tp;
    cudaGetSymbolAddress(&p_xq,   g_xq);
    cudaGetSymbolAddress(&p_xs,   g_xs);
    cudaGetSymbolAddress(&p_wc,   g_wc);
    cudaGetSymbolAddress(&p_meta, g_meta);
    cudaGetSymbolAddress(&p_lah,  g_lah);
    cudaGetSymbolAddress(&p_lbh,  g_lbh);
    cudaGetSymbolAddress(&p_tp,   g_tp);

    compress_w_kernel<<<(2048 * 256) / 256, 256>>>(w, (__half*)p_wc, (uint32_t*)p_meta);
    prep_lora_kernel<<<(2 * NL4) / 256, 256>>>(
        (const float4*)la, (const float4*)lb, (uint2*)p_lah, (uint2*)p_lbh);
    quant_x_kernel<<<(MROWS * IN_F / 8) / 256, 256>>>(x, smooth, (__half*)p_xs, (__half*)p_xq);

    void* fnp = nullptr;
    cudaDriverEntryPointQueryResult qr;
    cudaGetDriverEntryPointByVersion("cuTensorMapEncodeTiled", &fnp, 12000,
                                     cudaEnableDefault, &qr);
    tmap_fn_t enc = (tmap_fn_t)fnp;

    CUtensorMap ta, tb, tm, txs, tla;
    make_map_f16(enc, &ta,  p_wc, KDIM/2, OUT_F, TK/2, MO, CU_TENSOR_MAP_SWIZZLE_64B);
    make_map_f16(enc, &tb,  p_xq, KDIM,   MROWS, TK,   NM, CU_TENSOR_MAP_SWIZZLE_128B);
    make_map_f16(enc, &txs, p_xs, IN_F,   MROWS, 64,  128, CU_TENSOR_MAP_SWIZZLE_128B);
    make_map_f16(enc, &tla, p_lah, IN_F,  RANK,  64,   32, CU_TENSOR_MAP_SWIZZLE_128B);
    {
        cuuint64_t dims[2]    = {(cuuint64_t)(OUT_F/2), (cuuint64_t)(KDIM/16)};
        cuuint64_t strides[1] = {(cuuint64_t)(OUT_F/2) * 4};
        cuuint32_t es[2]      = {1, 1};
        cuuint32_t box[2]     = {64, 4};
        enc(&tm, CU_TENSOR_MAP_DATA_TYPE_UINT32, 2, p_meta, dims, strides, box, es,
            CU_TENSOR_MAP_INTERLEAVE_NONE, CU_TENSOR_MAP_SWIZZLE_NONE,
            CU_TENSOR_MAP_L2_PROMOTION_L2_128B, CU_TENSOR_MAP_FLOAT_OOB_FILL_NONE);
    }

    {
        dim3 lg(MROWS / 128, KSPLIT);
        lora_mma_kernel<<<lg, 160, L_SMEM>>>(txs, tla, (float*)p_tp);
    }

    cudaFuncSetAttribute(gemm_kernel, cudaFuncAttributeMaxDynamicSharedMemorySize, SMEM_TOTAL);
    dim3 grid(MROWS / NM, OUT_F / MO);
    gemm_kernel<<<grid, NTHR, SMEM_TOTAL>>>(ta, tb, tm, (const float*)p_tp,
                                            (const __half*)p_lbh, bias, out);
}

// round 16
// speedup vs baseline: 1.0299x; 1.0299x over previous
#include <cuda_runtime.h>
#include <cuda_fp16.h>
#include <cuda.h>
#include <cstdint>
#include <cstddef>

#define IN_F   4096
#define OUT_F  4096
#define MROWS  4096
#define RANK   32
#define KDIM   4096
#define TK     64
#define NKT    64
#define MO     128         // out-features per CTA (sparse A rows)
#define NM     128         // x-rows per CTA (B cols)
#define PSTG   3
#define KSPLIT 8
#define NTHR   288         // 8 consumer warps + 1 producer

#define A_STAGE_BYTES (MO*(TK/2)*2)     // 8192 (compressed, 64B rows)
#define B_STAGE_BYTES (NM*TK*2)         // 16384 (128B rows)
#define M_STAGE_BYTES 1024              // meta: 4 c-cols x 64 p x 4B
#define STAGE_BYTES   (A_STAGE_BYTES + B_STAGE_BYTES + M_STAGE_BYTES)  // 25600
#define SMEM_HDR      1024
#define OFF_LB        1024                          // 128*32*2 = 8192
#define OFF_T         (OFF_LB + MO*RANK*2)          // 9216; 128*32*2 = 8192
#define OFF_STAGE0    (OFF_T + NM*RANK*2)           // 17408
#define SMEM_TOTAL    (OFF_STAGE0 + PSTG*STAGE_BYTES)  // 94208 -> 2 CTAs/SM

__device__ __half   g_xq  [(size_t)MROWS * KDIM];
__device__ __half   g_xs  [(size_t)MROWS * IN_F];
__device__ __half   g_wc  [(size_t)OUT_F * (KDIM/2)];      // compressed 2:4 values
__device__ uint32_t g_meta[(size_t)(KDIM/16) * (OUT_F/2)]; // [256 c][2048 p]
__device__ __half   g_lah [(size_t)RANK * IN_F];
__device__ __half   g_lbh [(size_t)OUT_F * RANK];
__device__ float    g_tp  [(size_t)KSPLIT * MROWS * RANK];

__device__ __forceinline__ uint32_t smem_u32(const void* p) {
    uint32_t a;
    asm("{ .reg .u64 t; cvta.to.shared.u64 t, %1; cvt.u32.u64 %0, t; }" : "=r"(a) : "l"(p));
    return a;
}

#define MBAR_INIT(addr, cnt) \
    asm volatile("mbarrier.init.shared.b64 [%0], %1;" :: "r"(addr), "r"((uint32_t)(cnt)) : "memory")
#define MBAR_EXPECT_TX(addr, b) \
    asm volatile("mbarrier.arrive.expect_tx.shared.b64 _, [%0], %1;" :: "r"(addr), "r"((uint32_t)(b)) : "memory")
#define MBAR_ARRIVE(addr) \
    asm volatile("mbarrier.arrive.shared.b64 _, [%0];" :: "r"(addr) : "memory")
#define MBAR_WAIT(addr, ph) do {                                              \
    uint32_t _m = (addr), _p = (uint32_t)(ph), _d;                            \
    asm volatile("{\n\t.reg .pred p;\n\t"                                     \
        "mbarrier.try_wait.parity.acquire.cta.shared::cta.b64 p, [%1], %2;\n\t" \
        "selp.b32 %0, 1, 0, p;\n\t}"                                          \
        : "=r"(_d) : "r"(_m), "r"(_p) : "memory");                            \
    if (!_d) {                                                                \
        asm volatile("{\n\t.reg .pred P1;\n\t"                                \
            "WL%=:\n\t"                                                       \
            "mbarrier.try_wait.parity.acquire.cta.shared::cta.b64 P1, [%0], %1, 0x989680;\n\t" \
            "@P1 bra.uni WD%=;\n\t"                                           \
            "bra.uni WL%=;\n\t"                                               \
            "WD%=:\n\t}" :: "r"(_m), "r"(_p) : "memory");                     \
    }                                                                         \
} while (0)

__device__ __forceinline__ void tma_load_2d(uint32_t smem_addr, const CUtensorMap* map,
                                            int cx, int cy, uint32_t mbar) {
    asm volatile(
        "cp.async.bulk.tensor.2d.shared::cta.global.tile.mbarrier::complete_tx::bytes "
        "[%0], [%1, {%2, %3}], [%4];"
        :: "r"(smem_addr), "l"((unsigned long long)(uintptr_t)map),
           "r"(cx), "r"(cy), "r"(mbar) : "memory");
}

__device__ __forceinline__ void ldsm_x4(uint32_t& r0, uint32_t& r1, uint32_t& r2, uint32_t& r3,
                                        uint32_t addr) {
    asm volatile("ldmatrix.sync.aligned.m8n8.x4.shared.b16 {%0,%1,%2,%3}, [%4];"
                 : "=r"(r0), "=r"(r1), "=r"(r2), "=r"(r3) : "r"(addr));
}

__device__ __forceinline__ void mma16816(float* c, const uint32_t* a, uint32_t b0, uint32_t b1) {
    asm volatile(
        "mma.sync.aligned.m16n8k16.row.col.f32.f16.f16.f32 "
        "{%0,%1,%2,%3}, {%4,%5,%6,%7}, {%8,%9}, {%0,%1,%2,%3};"
        : "+f"(c[0]), "+f"(c[1]), "+f"(c[2]), "+f"(c[3])
        : "r"(a[0]), "r"(a[1]), "r"(a[2]), "r"(a[3]), "r"(b0), "r"(b1));
}

__device__ __forceinline__ void mma_sp16832(float* c, const uint32_t* a, const uint32_t* b,
                                            uint32_t e) {
    asm volatile(
        "mma.sp::ordered_metadata.sync.aligned.m16n8k32.row.col.f32.f16.f16.f32 "
        "{%0,%1,%2,%3}, {%4,%5,%6,%7}, {%8,%9,%10,%11}, {%0,%1,%2,%3}, %12, 0x0;"
        : "+f"(c[0]), "+f"(c[1]), "+f"(c[2]), "+f"(c[3])
        : "r"(a[0]), "r"(a[1]), "r"(a[2]), "r"(a[3]),
          "r"(b[0]), "r"(b[1]), "r"(b[2]), "r"(b[3]), "r"(e));
}

__device__ __forceinline__ float sel4(float v0, float v1, float v2, float v3, int i) {
    return (i == 0) ? v0 : (i == 1) ? v1 : (i == 2) ? v2 : v3;
}

// ---- fused prologue: [0,2048) compress W, [2048,2304) lora->fp16, [2304,6400) quant x ----
#define NL4 ((RANK * IN_F) / 4)
#define PRO_COMPRESS_BLKS 2048
#define PRO_LORA_BLKS     256
#define PRO_QUANT_BLKS    4096
#define PRO_TOTAL_BLKS    (PRO_COMPRESS_BLKS + PRO_LORA_BLKS + PRO_QUANT_BLKS)

__global__ void __launch_bounds__(256)
fused_prologue_kernel(const float* __restrict__ w,
                      const float* __restrict__ la,
                      const float* __restrict__ lb,
                      const float* __restrict__ x,
                      const float* __restrict__ ss,
                      __half* __restrict__ wc,
                      uint32_t* __restrict__ metap,
                      __half* __restrict__ lah,
                      __half* __restrict__ lbh,
                      __half* __restrict__ xs,
                      __half* __restrict__ xq) {
    int blk = blockIdx.x;
    if (blk < PRO_COMPRESS_BLKS) {
        // ---- compress W into 2:4 values + ordered metadata (R9-verified) ----
        int idx = blk * 256 + threadIdx.x;        // 2048 p * 256 c
        int p = idx >> 8;
        int c = idx & 255;
        int o0 = (p >> 3) * 16 + (p & 7);
        uint32_t meta32 = 0;
#pragma unroll
        for (int half_i = 0; half_i < 2; half_i++) {
            int o = o0 + half_i * 8;
            const float4* wr = reinterpret_cast<const float4*>(w + (size_t)o * KDIM + c * 16);
            __align__(16) __half st[8];
            uint32_t m16 = 0;
#pragma unroll
            for (int g = 0; g < 4; g++) {
                float4 v = wr[g];
                unsigned nz = (v.x != 0.0f ? 1u : 0u) | (v.y != 0.0f ? 2u : 0u)
                            | (v.z != 0.0f ? 4u : 0u) | (v.w != 0.0f ? 8u : 0u);
                int i0, i1;
                int n = __popc(nz);
                if (n >= 2) {
                    i0 = __ffs(nz) - 1;
                    unsigned rest = nz & ~(1u << i0);
                    i1 = __ffs(rest) - 1;
                } else if (n == 1) {
                    int ii = __ffs(nz) - 1;
                    if (ii == 3) { i0 = 2; i1 = 3; }
                    else         { i0 = ii; i1 = 3; }
                } else { i0 = 0; i1 = 1; }
                st[2*g]   = __float2half(sel4(v.x, v.y, v.z, v.w, i0));
                st[2*g+1] = __float2half(sel4(v.x, v.y, v.z, v.w, i1));
                m16 |= (uint32_t)(i0 | (i1 << 2)) << (4 * g);
            }
            reinterpret_cast<uint4*>(wc + (size_t)o * (KDIM/2) + c * 8)[0] =
                reinterpret_cast<uint4*>(st)[0];
            meta32 |= m16 << (16 * half_i);
        }
        metap[(size_t)c * (OUT_F/2) + p] = meta32;
    } else if (blk < PRO_COMPRESS_BLKS + PRO_LORA_BLKS) {
        // ---- lora_a, lora_b -> fp16 ----
        int idx = (blk - PRO_COMPRESS_BLKS) * 256 + threadIdx.x;
        float4 v; uint2* dst;
        if (idx < NL4) { v = reinterpret_cast<const float4*>(la)[idx];
                         dst = reinterpret_cast<uint2*>(lah) + idx; }
        else           { v = reinterpret_cast<const float4*>(lb)[idx - NL4];
                         dst = reinterpret_cast<uint2*>(lbh) + (idx - NL4); }
        __half2 lo = __floats2half2_rn(v.x, v.y);
        __half2 hi = __floats2half2_rn(v.z, v.w);
        uint2 o;
        o.x = *reinterpret_cast<uint32_t*>(&lo);
        o.y = *reinterpret_cast<uint32_t*>(&hi);
        *dst = o;
    } else {
        // ---- smooth + exact NVFP4 fake-quant (16 elems/thread, R13-verified) ----
        int b = (blk - PRO_COMPRESS_BLKS - PRO_LORA_BLKS) * 256 + threadIdx.x;
        int row = b >> 8;
        int kb  = (b & 255) << 4;
        const float4* xp = reinterpret_cast<const float4*>(x + (size_t)row * IN_F + kb);
        const float4* sp = reinterpret_cast<const float4*>(ss + kb);
        float v[16];
#pragma unroll
        for (int i = 0; i < 4; i++) {
            float4 a = xp[i]; float4 s = sp[i];
            v[4*i+0] = a.x * s.x; v[4*i+1] = a.y * s.y;
            v[4*i+2] = a.z * s.z; v[4*i+3] = a.w * s.w;
        }
        float amax = 0.0f;
#pragma unroll
        for (int i = 0; i < 16; i++) amax = fmaxf(amax, fabsf(v[i]));
        amax = fmaxf(amax, 1e-12f);
        float scale = amax / 6.0f;
        __align__(16) __half h_s[16];
        __align__(16) __half h_q[16];
#pragma unroll
        for (int i = 0; i < 16; i++) {
            h_s[i] = __float2half(v[i]);
            float an = fabsf(v[i]) / scale;
            float lvl;
            if      (an <= 0.25f) lvl = 0.0f;   // <= : tie -> lower level (argmin-first)
            else if (an <= 0.75f) lvl = 0.5f;
            else if (an <= 1.25f) lvl = 1.0f;
            else if (an <= 1.75f) lvl = 1.5f;
            else if (an <= 2.5f)  lvl = 2.0f;
            else if (an <= 3.5f)  lvl = 3.0f;
            else if (an <= 5.0f)  lvl = 4.0f;
            else                  lvl = 6.0f;
            h_q[i] = __float2half(copysignf(lvl * scale, v[i]));
        }
        uint4* d1 = reinterpret_cast<uint4*>(xs + (size_t)row * IN_F + kb);
        d1[0] = reinterpret_cast<uint4*>(h_s)[0];
        d1[1] = reinterpret_cast<uint4*>(h_s)[1];
        uint4* d2 = reinterpret_cast<uint4*>(xq + (size_t)row * KDIM + kb);
        d2[0] = reinterpret_cast<uint4*>(h_q)[0];
        d2[1] = reinterpret_cast<uint4*>(h_q)[1];
    }
}

// ---- prologue: t partials via mma (split-K; reduce folded into GEMM) ----
#define LPSTG 2
#define L_A_BYTES (128*64*2)
#define L_B_BYTES (32*64*2)
#define L_STAGE   (L_A_BYTES + L_B_BYTES)
#define L_SMEM    (1024 + LPSTG*L_STAGE)
#define LOFF_FULL(s)  (16u + 8u * (s))
#define LOFF_EMPTY(s) (48u + 8u * (s))
#define LOFF_A(s)     (1024u + (s) * L_STAGE)
#define LOFF_B(s)     (LOFF_A(s) + L_A_BYTES)

__global__ void __launch_bounds__(160, 1)
lora_mma_kernel(const __grid_constant__ CUtensorMap tma_xs,
                const __grid_constant__ CUtensorMap tma_la,
                float* __restrict__ tp) {
    extern __shared__ __align__(1024) char smem_buf[];
    uint32_t sbase = smem_u32(smem_buf);
    int tid  = threadIdx.x;
    int warp = tid >> 5;
    int lane = tid & 31;
    int m0 = blockIdx.x * 128;
    int kz = blockIdx.y;
    int kt0 = kz * 8;

    if (tid == 0) {
        for (int s = 0; s < LPSTG; s++) {
            MBAR_INIT(sbase + LOFF_FULL(s), 1);
            MBAR_INIT(sbase + LOFF_EMPTY(s), 4);
        }
    }
    __syncthreads();

    if (warp == 4) {
        if (lane == 0) {
            int s = 0;
            for (int kt = 0; kt < 8; kt++) {
                if (kt >= LPSTG) MBAR_WAIT(sbase + LOFF_EMPTY(s), ((kt - LPSTG) / LPSTG) & 1);
                MBAR_EXPECT_TX(sbase + LOFF_FULL(s), L_STAGE);
                tma_load_2d(sbase + LOFF_A(s), &tma_xs, (kt0 + kt) * 64, m0, sbase + LOFF_FULL(s));
                tma_load_2d(sbase + LOFF_B(s), &tma_la, (kt0 + kt) * 64, 0,  sbase + LOFF_FULL(s));
                if (++s == LPSTG) s = 0;
            }
        }
        return;
    }

    int wm = warp * 32;
    int lrow = (lane & 7) + ((lane >> 3) & 1) * 8;
    int lhi  = (lane >> 4) & 1;
    uint32_t arow[2], asw[2], brow[2], bsw[2];
#pragma unroll
    for (int i = 0; i < 2; i++) {
        int ra = wm + i * 16 + lrow;
        arow[i] = (uint32_t)ra * 128u; asw[i] = (uint32_t)(ra & 7);
        int rb = i * 16 + lrow;
        brow[i] = (uint32_t)rb * 128u; bsw[i] = (uint32_t)(rb & 7);
    }
    float acc[2][4][4];
#pragma unroll
    for (int i = 0; i < 2; i++)
#pragma unroll
        for (int j = 0; j < 4; j++)
#pragma unroll
            for (int q = 0; q < 4; q++) acc[i][j][q] = 0.0f;

    int s = 0;
    for (int kt = 0; kt < 8; kt++) {
        MBAR_WAIT(sbase + LOFF_FULL(s), (kt / LPSTG) & 1);
        uint32_t aS = sbase + LOFF_A(s);
        uint32_t bS = sbase + LOFF_B(s);
#pragma unroll
        for (int ks = 0; ks < 4; ks++) {
            uint32_t chunk = (uint32_t)(ks * 2 + lhi);
            uint32_t a[2][4];
            uint32_t bf[4][2];
#pragma unroll
            for (int mi = 0; mi < 2; mi++)
                ldsm_x4(a[mi][0], a[mi][1], a[mi][2], a[mi][3],
                        aS + arow[mi] + (((chunk ^ asw[mi]) & 7u) << 4));
#pragma unroll
            for (int nj = 0; nj < 2; nj++) {
                uint32_t r0, r1, r2, r3;
                ldsm_x4(r0, r1, r2, r3,
                        bS + brow[nj] + (((chunk ^ bsw[nj]) & 7u) << 4));
                bf[2*nj][0] = r0; bf[2*nj][1] = r2;
                bf[2*nj+1][0] = r1; bf[2*nj+1][1] = r3;
            }
#pragma unroll
            for (int mi = 0; mi < 2; mi++)
#pragma unroll
                for (int ni = 0; ni < 4; ni++)
                    mma16816(acc[mi][ni], a[mi], bf[ni][0], bf[ni][1]);
        }
        if (lane == 0) MBAR_ARRIVE(sbase + LOFF_EMPTY(s));
        if (++s == LPSTG) s = 0;
    }

    float* tpb = tp + (size_t)kz * MROWS * RANK;
    int crow = lane >> 2;
    int ccol = (lane & 3) * 2;
#pragma unroll
    for (int mi = 0; mi < 2; mi++) {
        int m = m0 + wm + mi * 16 + crow;
#pragma unroll
        for (int ni = 0; ni < 4; ni++) {
            int c = ni * 8 + ccol;
            *reinterpret_cast<float2*>(tpb + (size_t)m * RANK + c) =
                make_float2(acc[mi][ni][0], acc[mi][ni][1]);
            *reinterpret_cast<float2*>(tpb + (size_t)(m + 8) * RANK + c) =
                make_float2(acc[mi][ni][2], acc[mi][ni][3]);
        }
    }
}

// ---- main sparse GEMM: MO=128 out x NM=128 m, 8 consumer warps (64x32), 2 CTA/SM ----
#define OFF_FULL(s)  (16u + 8u * (s))
#define OFF_EMPTY(s) (64u + 8u * (s))
#define OFF_A(s)     (OFF_STAGE0 + (s) * STAGE_BYTES)
#define OFF_B(s)     (OFF_A(s) + A_STAGE_BYTES)
#define OFF_M(s)     (OFF_B(s) + B_STAGE_BYTES)

__global__ void __launch_bounds__(NTHR, 2)
gemm_kernel(const __grid_constant__ CUtensorMap tma_a,
            const __grid_constant__ CUtensorMap tma_b,
            const __grid_constant__ CUtensorMap tma_m,
            const float* __restrict__ tp,
            const __half* __restrict__ lbh,
            const float* __restrict__ bias,
            float* __restrict__ out) {
    extern __shared__ __align__(1024) char smem_buf[];
    uint32_t sbase = smem_u32(smem_buf);
    int tid  = threadIdx.x;
    int warp = tid >> 5;
    int lane = tid & 31;
    int m0g = blockIdx.x * NM;     // x-rows base
    int mo0 = blockIdx.y * MO;     // out-features base

    // lb tile [MO x 32] fp16 (coop), t tile [NM x 32] fp16 built from partials
    {
        const uint4* lbg = reinterpret_cast<const uint4*>(lbh + (size_t)mo0 * RANK);
        uint4* lbs = reinterpret_cast<uint4*>(smem_buf + OFF_LB);
        for (int i = tid; i < MO * 4; i += NTHR) lbs[i] = lbg[i];
        for (int i = tid; i < NM * RANK; i += NTHR) {
            int r = i >> 5, c = i & 31;
            float s = 0.0f;
#pragma unroll
            for (int z = 0; z < KSPLIT; z++)
                s += tp[(size_t)z * MROWS * RANK + (size_t)(m0g + r) * RANK + c];
            *reinterpret_cast<__half*>(smem_buf + OFF_T + r * 64 + c * 2) = __float2half(s);
        }
    }
    if (tid == 0) {
        for (int s = 0; s < PSTG; s++) {
            MBAR_INIT(sbase + OFF_FULL(s), 1);
            MBAR_INIT(sbase + OFF_EMPTY(s), 8);
        }
    }
    __syncthreads();

    int wo = (warp & 1) * 64;       // out offset (A rows), 2 groups
    int wm = (warp >> 1) * 32;      // m offset (B cols), 4 groups  [warp 8 = producer]
    float acc[4][4][4];

    if (warp == 8) {
        if (lane == 0) {
            int s = 0;
            for (int kt = 0; kt < NKT; kt++) {
                if (kt >= PSTG) MBAR_WAIT(sbase + OFF_EMPTY(s), ((kt - PSTG) / PSTG) & 1);
                MBAR_EXPECT_TX(sbase + OFF_FULL(s), STAGE_BYTES);
                tma_load_2d(sbase + OFF_A(s), &tma_a, kt * (TK/2), mo0, sbase + OFF_FULL(s));
                tma_load_2d(sbase + OFF_B(s), &tma_b, kt * TK, m0g, sbase + OFF_FULL(s));
                tma_load_2d(sbase + OFF_M(s), &tma_m, mo0 >> 1, kt * 4, sbase + OFF_FULL(s));
                if (++s == PSTG) s = 0;
            }
        }
    } else {
#pragma unroll
        for (int i = 0; i < 4; i++)
#pragma unroll
            for (int j = 0; j < 4; j++)
#pragma unroll
                for (int q = 0; q < 4; q++) acc[i][j][q] = 0.0f;

        // A (compressed) lane addressing: 64B rows, SW64
        int Lm = lane >> 3;
        int amrow = (Lm & 1) * 8 + (lane & 7);
        int achunk_add = Lm >> 1;
        uint32_t arowb[4], akey[4];
#pragma unroll
        for (int mi = 0; mi < 4; mi++) {
            int r = wo + mi * 16 + amrow;
            arowb[mi] = (uint32_t)r * 64u;
            akey[mi]  = (uint32_t)((r >> 1) & 3);
        }
        // B lane addressing: 128B rows, SW128
        int lrow = (lane & 7) + ((lane >> 3) & 1) * 8;
        int lhi  = (lane >> 4) & 1;
        uint32_t browb[2], bkey[2];
#pragma unroll
        for (int g = 0; g < 2; g++) {
            int r = wm + g * 16 + lrow;
            browb[g] = (uint32_t)r * 128u;
            bkey[g]  = (uint32_t)(r & 7);
        }
        // metadata (smem): meta tile [4 c-cols x 64 p], row stride 256B
        uint32_t mploc = (uint32_t)(wo / 2 + (lane >> 2)) * 4u;
        uint32_t cpar  = (uint32_t)(lane & 1);

        int s = 0;
        for (int kt = 0; kt < NKT; kt++) {
            MBAR_WAIT(sbase + OFF_FULL(s), (kt / PSTG) & 1);
            uint32_t aS = sbase + OFF_A(s);
            uint32_t bS = sbase + OFF_B(s);
            uint32_t mS = sbase + OFF_M(s);
#pragma unroll
            for (int kk = 0; kk < 2; kk++) {
                uint32_t mreg[4];
                uint32_t mcol = mS + ((uint32_t)(kk * 2) + cpar) * 256u + mploc;
#pragma unroll
                for (int mi = 0; mi < 4; mi++)
                    asm volatile("ld.shared.b32 %0, [%1];"
                                 : "=r"(mreg[mi]) : "r"(mcol + (uint32_t)mi * 32u));
                uint32_t a[4][4];
#pragma unroll
                for (int mi = 0; mi < 4; mi++) {
                    uint32_t c = (uint32_t)(kk * 2 + achunk_add);
                    ldsm_x4(a[mi][0], a[mi][1], a[mi][2], a[mi][3],
                            aS + arowb[mi] + (((c ^ akey[mi]) & 3u) << 4));
                }
                uint32_t bf[4][4];
#pragma unroll
                for (int g = 0; g < 2; g++) {
#pragma unroll
                    for (int sub = 0; sub < 2; sub++) {
                        uint32_t chunk = (uint32_t)(kk * 4 + sub * 2 + lhi);
                        uint32_t r0, r1, r2, r3;
                        ldsm_x4(r0, r1, r2, r3,
                                bS + browb[g] + (((chunk ^ bkey[g]) & 7u) << 4));
                        bf[2*g][2*sub]     = r0; bf[2*g][2*sub+1]   = r2;
                        bf[2*g+1][2*sub]   = r1; bf[2*g+1][2*sub+1] = r3;
                    }
                }
#pragma unroll
                for (int mi = 0; mi < 4; mi++)
#pragma unroll
                    for (int ni = 0; ni < 4; ni++)
                        mma_sp16832(acc[mi][ni], a[mi], bf[ni], mreg[mi]);
            }
            if (lane == 0) MBAR_ARRIVE(sbase + OFF_EMPTY(s));
            if (++s == PSTG) s = 0;
        }

        // ---- LoRA correction: acc += lb_tile @ t_tile^T (dense, K=32) ----
        {
            uint32_t lbS = sbase + OFF_LB;
            uint32_t tS  = sbase + OFF_T;
#pragma unroll
            for (int kk = 0; kk < 2; kk++) {
                uint32_t a[4][4];
#pragma unroll
                for (int mi = 0; mi < 4; mi++) {
                    int r = wo + mi * 16 + amrow;
                    uint32_t c = (uint32_t)(kk * 2 + achunk_add);
                    ldsm_x4(a[mi][0], a[mi][1], a[mi][2], a[mi][3],
                            lbS + (uint32_t)r * 64u + (c << 4));
                }
                uint32_t bf[4][2];
#pragma unroll
                for (int g = 0; g < 2; g++) {
                    int r = wm + g * 16 + lrow;
                    uint32_t chunk = (uint32_t)(kk * 2 + lhi);
                    uint32_t r0, r1, r2, r3;
                    ldsm_x4(r0, r1, r2, r3, tS + (uint32_t)r * 64u + (chunk << 4));
                    bf[2*g][0] = r0; bf[2*g][1] = r2;
                    bf[2*g+1][0] = r1; bf[2*g+1][1] = r3;
                }
#pragma unroll
                for (int mi = 0; mi < 4; mi++)
#pragma unroll
                    for (int ni = 0; ni < 4; ni++)
                        mma16816(acc[mi][ni], a[mi], bf[ni][0], bf[ni][1]);
            }
        }
    }

    __syncthreads();   // all stages consumed; reuse smem for transpose

    if (warp < 8) {
        float* tw = reinterpret_cast<float*>(smem_buf + SMEM_HDR) + warp * (32 * 68);
        int crow = lane >> 2;
        int ccol = (lane & 3) * 2;
#pragma unroll
        for (int mi = 0; mi < 4; mi++) {
            int o0 = mi * 16 + crow;
#pragma unroll
            for (int ni = 0; ni < 4; ni++) {
                int ml = ni * 8 + ccol;
                tw[ml * 68 + o0]           = acc[mi][ni][0];
                tw[(ml + 1) * 68 + o0]     = acc[mi][ni][1];
                tw[ml * 68 + o0 + 8]       = acc[mi][ni][2];
                tw[(ml + 1) * 68 + o0 + 8] = acc[mi][ni][3];
            }
        }
        __syncwarp();
        int oc = (lane & 15) * 4;
        float4 bv = __ldg(reinterpret_cast<const float4*>(bias + mo0 + wo + oc));
#pragma unroll 4
        for (int it = 0; it < 16; it++) {
            int ml = it * 2 + (lane >> 4);
            float4 v = *reinterpret_cast<float4*>(tw + ml * 68 + oc);
            v.x += bv.x; v.y += bv.y; v.z += bv.z; v.w += bv.w;
            *reinterpret_cast<float4*>(out + (size_t)(m0g + wm + ml) * OUT_F + mo0 + wo + oc) = v;
        }
    }
}

typedef CUresult (*tmap_fn_t)(CUtensorMap*, CUtensorMapDataType, cuuint32_t, void*,
                              const cuuint64_t*, const cuuint64_t*, const cuuint32_t*,
                              const cuuint32_t*, CUtensorMapInterleave, CUtensorMapSwizzle,
                              CUtensorMapL2promotion, CUtensorMapFloatOOBfill);

static void make_map_f16(tmap_fn_t enc, CUtensorMap* m, void* ptr,
                         uint64_t d0, uint64_t d1, uint32_t b0, uint32_t b1,
                         CUtensorMapSwizzle sw) {
    cuuint64_t dims[2]    = {(cuuint64_t)d0, (cuuint64_t)d1};
    cuuint64_t strides[1] = {(cuuint64_t)d0 * 2};
    cuuint32_t es[2]      = {1, 1};
    cuuint32_t box[2]     = {b0, b1};
    enc(m, CU_TENSOR_MAP_DATA_TYPE_FLOAT16, 2, ptr, dims, strides, box, es,
        CU_TENSOR_MAP_INTERLEAVE_NONE, sw,
        CU_TENSOR_MAP_L2_PROMOTION_L2_128B, CU_TENSOR_MAP_FLOAT_OOB_FILL_NONE);
}

extern "C" void kernel_launch(void* const* d_in, const int* in_sizes, int n_in,
                              void* d_out, int out_size) {
    (void)in_sizes; (void)n_in; (void)out_size;
    const float* x      = (const float*)d_in[0];
    const float* smooth = (const float*)d_in[1];
    const float* w      = (const float*)d_in[2];
    const float* la     = (const float*)d_in[3];
    const float* lb     = (const float*)d_in[4];
    const float* bias   = (const float*)d_in[5];
    float* out = (float*)d_out;

    void *p_xq, *p_xs, *p_wc, *p_meta, *p_lah, *p_lbh, *p_tp;
    cudaGetSymbolAddress(&p_xq,   g_xq);
    cudaGetSymbolAddress(&p_xs,   g_xs);
    cudaGetSymbolAddress(&p_wc,   g_wc);
    cudaGetSymbolAddress(&p_meta, g_meta);
    cudaGetSymbolAddress(&p_lah,  g_lah);
    cudaGetSymbolAddress(&p_lbh,  g_lbh);
    cudaGetSymbolAddress(&p_tp,   g_tp);

    fused_prologue_kernel<<<PRO_TOTAL_BLKS, 256>>>(
        w, la, lb, x, smooth,
        (__half*)p_wc, (uint32_t*)p_meta, (__half*)p_lah, (__half*)p_lbh,
        (__half*)p_xs, (__half*)p_xq);

    void* fnp = nullptr;
    cudaDriverEntryPointQueryResult qr;
    cudaGetDriverEntryPointByVersion("cuTensorMapEncodeTiled", &fnp, 12000,
                                     cudaEnableDefault, &qr);
    tmap_fn_t enc = (tmap_fn_t)fnp;

    CUtensorMap ta, tb, tm, txs, tla;
    make_map_f16(enc, &ta,  p_wc, KDIM/2, OUT_F, TK/2, MO, CU_TENSOR_MAP_SWIZZLE_64B);
    make_map_f16(enc, &tb,  p_xq, KDIM,   MROWS, TK,   NM, CU_TENSOR_MAP_SWIZZLE_128B);
    make_map_f16(enc, &txs, p_xs, IN_F,   MROWS, 64,  128, CU_TENSOR_MAP_SWIZZLE_128B);
    make_map_f16(enc, &tla, p_lah, IN_F,  RANK,  64,   32, CU_TENSOR_MAP_SWIZZLE_128B);
    {
        cuuint64_t dims[2]    = {(cuuint64_t)(OUT_F/2), (cuuint64_t)(KDIM/16)};
        cuuint64_t strides[1] = {(cuuint64_t)(OUT_F/2) * 4};
        cuuint32_t es[2]      = {1, 1};
        cuuint32_t box[2]     = {64, 4};
        enc(&tm, CU_TENSOR_MAP_DATA_TYPE_UINT32, 2, p_meta, dims, strides, box, es,
            CU_TENSOR_MAP_INTERLEAVE_NONE, CU_TENSOR_MAP_SWIZZLE_NONE,
            CU_TENSOR_MAP_L2_PROMOTION_L2_128B, CU_TENSOR_MAP_FLOAT_OOB_FILL_NONE);
    }

    {
        dim3 lg(MROWS / 128, KSPLIT);
        lora_mma_kernel<<<lg, 160, L_SMEM>>>(txs, tla, (float*)p_tp);
    }

    cudaFuncSetAttribute(gemm_kernel, cudaFuncAttributeMaxDynamicSharedMemorySize, SMEM_TOTAL);
    dim3 grid(MROWS / NM, OUT_F / MO);
    gemm_kernel<<<grid, NTHR, SMEM_TOTAL>>>(ta, tb, tm, (const float*)p_tp,
                                            (const __half*)p_lbh, bias, out);
}